// round 10
// baseline (speedup 1.0000x reference)
#include <cuda_runtime.h>
#include <cuda_fp16.h>

#define NB 50000
#define EE 1600000
#define ET (EE + NB)
#define GG 128

// ---------------- device scratch (no allocations allowed) ----------------
__device__ __align__(16) int    g_csr[ET];          // src ids sorted by dst
__device__ __align__(16) int    g_deg[NB + 1];
__device__ __align__(16) int    g_off[NB + 1];
__device__ __align__(16) int    g_cur[NB];
__device__ __align__(16) float  g_h[NB * 64];       // W-transformed features (fp32)
__device__ __align__(16) __half g_h16[NB * 64];     // fp16 mirror for edge gathers
__device__ __align__(16) float  g_act[NB * 64];     // activated layer output / next input
__device__ __align__(16) float  g_asrc[NB * 8];
__device__ __align__(16) float  g_adst[NB * 8];
__device__ __align__(16) float  g_pool[GG * 32];
__device__ __align__(16) float  g_cnt[GG];

// ---------------- graph build ----------------
__global__ void k_zero() {
    int i = blockIdx.x * blockDim.x + threadIdx.x;
    if (i <= NB) g_deg[i] = 0;
    if (i < GG * 32) g_pool[i] = 0.f;
    if (i < GG) g_cnt[i] = 0.f;
}

__global__ void k_count(const int* __restrict__ ei) {
    int i = blockIdx.x * blockDim.x + threadIdx.x;
    if (i >= ET) return;
    int d = (i < EE) ? ei[EE + i] : (i - EE);
    atomicAdd(&g_deg[d], 1);
}

__global__ void k_scan() {   // 1 block, 1024 threads: exclusive scan of g_deg
    __shared__ int sm[1024];
    const int C = 49;                       // 49*1024 >= NB
    int t = threadIdx.x;
    int start = t * C;
    int end = min(start + C, NB);
    int sum = 0;
    for (int i = start; i < end; i++) sum += g_deg[i];
    sm[t] = sum;
    __syncthreads();
    for (int d = 1; d < 1024; d <<= 1) {
        int v = (t >= d) ? sm[t - d] : 0;
        __syncthreads();
        sm[t] += v;
        __syncthreads();
    }
    int run = (t == 0) ? 0 : sm[t - 1];
    for (int i = start; i < end; i++) {
        g_off[i] = run; g_cur[i] = run;
        run += g_deg[i];
    }
    if (t == 0) g_off[NB] = sm[1023];
}

__global__ void k_scatter(const int* __restrict__ ei) {
    int i = blockIdx.x * blockDim.x + threadIdx.x;
    if (i >= ET) return;
    int s, d;
    if (i < EE) { s = ei[i]; d = ei[EE + i]; }
    else        { s = i - EE; d = s; }
    int pos = atomicAdd(&g_cur[d], 1);
    g_csr[pos] = s;
}

// ---------------- dense: h = X @ W  (writes g_h) ----------------
template <int K, int J, int RB, bool USE_ACT>
__global__ void k_gemm(const float* __restrict__ Xparam, const float* __restrict__ W) {
    const float* __restrict__ X = USE_ACT ? (const float*)g_act : Xparam;
    constexpr int CG = J / 4;                 // column groups (4 cols each)
    constexpr int RPT = RB * CG / 256;        // rows per thread
    __shared__ float sW[K * J];
    __shared__ float sX[RB * K];
    int t = threadIdx.x;
    int row0 = blockIdx.x * RB;
    for (int i = t; i < K * J; i += 256) sW[i] = W[i];
    int nrows = min(RB, NB - row0);
    for (int i = t; i < nrows * K; i += 256) sX[i] = X[(size_t)row0 * K + i];
    __syncthreads();

    int rg = t / CG, cg = t % CG;
    float acc[RPT][4];
#pragma unroll
    for (int r = 0; r < RPT; r++)
#pragma unroll
        for (int q = 0; q < 4; q++) acc[r][q] = 0.f;

#pragma unroll 8
    for (int k = 0; k < K; k++) {
        float xs[RPT];
#pragma unroll
        for (int r = 0; r < RPT; r++) xs[r] = sX[(rg * RPT + r) * K + k];
#pragma unroll
        for (int q = 0; q < 4; q++) {
            float w = sW[k * J + cg + CG * q];
#pragma unroll
            for (int r = 0; r < RPT; r++) acc[r][q] = fmaf(xs[r], w, acc[r][q]);
        }
    }
#pragma unroll
    for (int r = 0; r < RPT; r++) {
        int row = row0 + rg * RPT + r;
        if (row < NB) {
#pragma unroll
            for (int q = 0; q < 4; q++) g_h[(size_t)row * J + cg + CG * q] = acc[r][q];
        }
    }
}

// ---------------- attention coefficients (8 heads x 8 ch) + fp16 mirror ----------------
__global__ void k_attn(const float* __restrict__ As, const float* __restrict__ Ad) {
    int idx = blockIdx.x * blockDim.x + threadIdx.x;   // n*8 + head
    if (idx >= NB * 8) return;
    int h = idx & 7;
    const float4* hp = (const float4*)(g_h + (size_t)idx * 8);
    float4 v0 = hp[0], v1 = hp[1];
    const float4* ap = (const float4*)(As + h * 8);
    float4 a0 = __ldg(ap), a1 = __ldg(ap + 1);
    const float4* bp = (const float4*)(Ad + h * 8);
    float4 c0 = __ldg(bp), c1 = __ldg(bp + 1);
    g_asrc[idx] = v0.x*a0.x + v0.y*a0.y + v0.z*a0.z + v0.w*a0.w
                + v1.x*a1.x + v1.y*a1.y + v1.z*a1.z + v1.w*a1.w;
    g_adst[idx] = v0.x*c0.x + v0.y*c0.y + v0.z*c0.z + v0.w*c0.w
                + v1.x*c1.x + v1.y*c1.y + v1.z*c1.z + v1.w*c1.w;
    union { __half2 h2[4]; uint4 u4; } pk;
    pk.h2[0] = __floats2half2_rn(v0.x, v0.y);
    pk.h2[1] = __floats2half2_rn(v0.z, v0.w);
    pk.h2[2] = __floats2half2_rn(v1.x, v1.y);
    pk.h2[3] = __floats2half2_rn(v1.z, v1.w);
    *(uint4*)(g_h16 + (size_t)idx * 8) = pk.u4;
}

// ---------------- softmax-aggregate: warp per dst node, MLP-4 pipelined ----------------
__global__ void k_agg(const float* __restrict__ B) {
    int gw = (blockIdx.x * blockDim.x + threadIdx.x) >> 5;
    if (gw >= NB) return;
    int lane = threadIdx.x & 31;
    int head = lane >> 2;
    int begin = g_off[gw], end = g_off[gw + 1];
    float ad = g_adst[gw * 8 + head];
    int j = lane * 2;                              // channel pair: head*8 + (lane%4)*2
    const __half2* __restrict__ h2p = (const __half2*)g_h16;

    float s = 0.f, ax = 0.f, ay = 0.f;
    int i = begin;
    for (; i + 4 <= end; i += 4) {
        // 4 independent index loads
        int s0 = __ldg(&g_csr[i]);
        int s1 = __ldg(&g_csr[i + 1]);
        int s2 = __ldg(&g_csr[i + 2]);
        int s3 = __ldg(&g_csr[i + 3]);
        // 8 independent gathers (asrc + h), all issued back-to-back
        float e0 = __ldg(&g_asrc[s0 * 8 + head]);
        float e1 = __ldg(&g_asrc[s1 * 8 + head]);
        float e2 = __ldg(&g_asrc[s2 * 8 + head]);
        float e3 = __ldg(&g_asrc[s3 * 8 + head]);
        __half2 q0 = __ldg(&h2p[s0 * 32 + lane]);
        __half2 q1 = __ldg(&h2p[s1 * 32 + lane]);
        __half2 q2 = __ldg(&h2p[s2 * 32 + lane]);
        __half2 q3 = __ldg(&h2p[s3 * 32 + lane]);

        e0 += ad; e0 = (e0 >= 0.f) ? e0 : 0.2f * e0; float p0 = __expf(fminf(e0, 80.f));
        e1 += ad; e1 = (e1 >= 0.f) ? e1 : 0.2f * e1; float p1 = __expf(fminf(e1, 80.f));
        e2 += ad; e2 = (e2 >= 0.f) ? e2 : 0.2f * e2; float p2 = __expf(fminf(e2, 80.f));
        e3 += ad; e3 = (e3 >= 0.f) ? e3 : 0.2f * e3; float p3 = __expf(fminf(e3, 80.f));
        s += (p0 + p1) + (p2 + p3);
        float2 f0 = __half22float2(q0); ax = fmaf(p0, f0.x, ax); ay = fmaf(p0, f0.y, ay);
        float2 f1 = __half22float2(q1); ax = fmaf(p1, f1.x, ax); ay = fmaf(p1, f1.y, ay);
        float2 f2 = __half22float2(q2); ax = fmaf(p2, f2.x, ax); ay = fmaf(p2, f2.y, ay);
        float2 f3 = __half22float2(q3); ax = fmaf(p3, f3.x, ax); ay = fmaf(p3, f3.y, ay);
    }
    for (; i < end; i++) {
        int src = __ldg(&g_csr[i]);
        float e = __ldg(&g_asrc[src * 8 + head]) + ad;
        e = (e >= 0.f) ? e : 0.2f * e;
        float p = __expf(fminf(e, 80.f));
        float2 hv = __half22float2(__ldg(&h2p[src * 32 + lane]));
        s += p;
        ax = fmaf(p, hv.x, ax);
        ay = fmaf(p, hv.y, ay);
    }
    float inv = 1.f / (s + 1e-16f);
    float ox = ax * inv + B[j];
    float oy = ay * inv + B[j + 1];
    ox = (ox > 0.f) ? ox : (__expf(ox) - 1.f);     // ELU
    oy = (oy > 0.f) ? oy : (__expf(oy) - 1.f);
    *(float2*)(g_act + (size_t)gw * 64 + j) = make_float2(ox, oy);
}

// ---------------- final layer: 1 head, 32 channels ----------------
__global__ void k_attn_final(const float* __restrict__ As, const float* __restrict__ Ad) {
    int n = blockIdx.x * blockDim.x + threadIdx.x;
    if (n >= NB) return;
    const float4* hp = (const float4*)(g_h + (size_t)n * 32);
    float s = 0.f, d = 0.f;
    union { __half2 h2[2]; uint2 u2; } pk;
#pragma unroll
    for (int q = 0; q < 8; q++) {
        float4 hv = hp[q];
        float4 av = __ldg((const float4*)As + q);
        float4 dv = __ldg((const float4*)Ad + q);
        s += hv.x*av.x + hv.y*av.y + hv.z*av.z + hv.w*av.w;
        d += hv.x*dv.x + hv.y*dv.y + hv.z*dv.z + hv.w*dv.w;
        pk.h2[0] = __floats2half2_rn(hv.x, hv.y);
        pk.h2[1] = __floats2half2_rn(hv.z, hv.w);
        *(uint2*)(g_h16 + (size_t)n * 32 + q * 4) = pk.u2;
    }
    g_asrc[n] = s; g_adst[n] = d;
}

// single pass + fused global mean-pool accumulation, MLP-4 pipelined
__global__ void k_agg_final(const float* __restrict__ Bf, const int* __restrict__ batch) {
    int gw = (blockIdx.x * blockDim.x + threadIdx.x) >> 5;
    if (gw >= NB) return;
    int lane = threadIdx.x & 31;
    int begin = g_off[gw], end = g_off[gw + 1];
    float ad = g_adst[gw];

    float s = 0.f, acc = 0.f;
    int i = begin;
    for (; i + 4 <= end; i += 4) {
        int s0 = __ldg(&g_csr[i]);
        int s1 = __ldg(&g_csr[i + 1]);
        int s2 = __ldg(&g_csr[i + 2]);
        int s3 = __ldg(&g_csr[i + 3]);
        float e0 = __ldg(&g_asrc[s0]);
        float e1 = __ldg(&g_asrc[s1]);
        float e2 = __ldg(&g_asrc[s2]);
        float e3 = __ldg(&g_asrc[s3]);
        __half q0 = __ldg(&g_h16[(size_t)s0 * 32 + lane]);
        __half q1 = __ldg(&g_h16[(size_t)s1 * 32 + lane]);
        __half q2 = __ldg(&g_h16[(size_t)s2 * 32 + lane]);
        __half q3 = __ldg(&g_h16[(size_t)s3 * 32 + lane]);

        e0 += ad; e0 = (e0 >= 0.f) ? e0 : 0.2f * e0; float p0 = __expf(fminf(e0, 80.f));
        e1 += ad; e1 = (e1 >= 0.f) ? e1 : 0.2f * e1; float p1 = __expf(fminf(e1, 80.f));
        e2 += ad; e2 = (e2 >= 0.f) ? e2 : 0.2f * e2; float p2 = __expf(fminf(e2, 80.f));
        e3 += ad; e3 = (e3 >= 0.f) ? e3 : 0.2f * e3; float p3 = __expf(fminf(e3, 80.f));
        s += (p0 + p1) + (p2 + p3);
        acc = fmaf(p0, __half2float(q0), acc);
        acc = fmaf(p1, __half2float(q1), acc);
        acc = fmaf(p2, __half2float(q2), acc);
        acc = fmaf(p3, __half2float(q3), acc);
    }
    for (; i < end; i++) {
        int src = __ldg(&g_csr[i]);
        float e = __ldg(&g_asrc[src]) + ad;
        e = (e >= 0.f) ? e : 0.2f * e;
        float p = __expf(fminf(e, 80.f));
        s += p;
        acc = fmaf(p, __half2float(__ldg(&g_h16[(size_t)src * 32 + lane])), acc);
    }
    float o = acc / (s + 1e-16f) + Bf[lane];
    int g = batch[gw];
    atomicAdd(&g_pool[g * 32 + lane], o);
    if (lane == 0) atomicAdd(&g_cnt[g], 1.f);
}

// ---------------- head ----------------
__global__ void k_final(const float* __restrict__ Wl, const float* __restrict__ bl,
                        float* __restrict__ out) {
    int t = blockIdx.x * blockDim.x + threadIdx.x;
    if (t >= GG * 2) return;
    int g = t >> 1, o = t & 1;
    float cnt = fmaxf(g_cnt[g], 1.f);
    float acc = 0.f;
#pragma unroll
    for (int c = 0; c < 32; c++) acc += g_pool[g * 32 + c] * Wl[c * 2 + o];
    out[t] = acc / cnt + bl[o];
}

// ---------------- launcher ----------------
extern "C" void kernel_launch(void* const* d_in, const int* in_sizes, int n_in,
                              void* d_out, int out_size) {
    const float* x     = (const float*)d_in[0];
    const int*   ei    = (const int*)d_in[1];      // int32
    const int*   batch = (const int*)d_in[2];      // int32
    const float* W0 = (const float*)d_in[3];
    const float* as0 = (const float*)d_in[4];
    const float* ad0 = (const float*)d_in[5];
    const float* b0 = (const float*)d_in[6];
    const float* W1 = (const float*)d_in[7];
    const float* as1 = (const float*)d_in[8];
    const float* ad1 = (const float*)d_in[9];
    const float* b1 = (const float*)d_in[10];
    const float* W2 = (const float*)d_in[11];
    const float* as2 = (const float*)d_in[12];
    const float* ad2 = (const float*)d_in[13];
    const float* b2 = (const float*)d_in[14];
    const float* Wf = (const float*)d_in[15];
    const float* asf = (const float*)d_in[16];
    const float* adf = (const float*)d_in[17];
    const float* bf = (const float*)d_in[18];
    const float* Wl = (const float*)d_in[19];
    const float* bl = (const float*)d_in[20];
    float* out = (float*)d_out;

    // graph prep (dst is identical across layers -> one CSR build per launch)
    k_zero<<<(NB + 256) / 256, 256>>>();
    k_count<<<(ET + 255) / 256, 256>>>(ei);
    k_scan<<<1, 1024>>>();
    k_scatter<<<(ET + 255) / 256, 256>>>(ei);

    const int ATTN_GRID = (NB * 8 + 255) / 256;
    const int AGG_GRID  = (NB * 32 + 255) / 256;

    // layer 0: 128 -> 8x8   (RB=32: 48KB smem)
    k_gemm<128, 64, 32, false><<<(NB + 31) / 32, 256>>>(x, W0);
    k_attn<<<ATTN_GRID, 256>>>(as0, ad0);
    k_agg<<<AGG_GRID, 256>>>(b0);
    // layer 1  (RB=64: 32KB smem)
    k_gemm<64, 64, 64, true><<<(NB + 63) / 64, 256>>>(nullptr, W1);
    k_attn<<<ATTN_GRID, 256>>>(as1, ad1);
    k_agg<<<AGG_GRID, 256>>>(b1);
    // layer 2
    k_gemm<64, 64, 64, true><<<(NB + 63) / 64, 256>>>(nullptr, W2);
    k_attn<<<ATTN_GRID, 256>>>(as2, ad2);
    k_agg<<<AGG_GRID, 256>>>(b2);
    // final conv: 64 -> 32, 1 head
    k_gemm<64, 32, 64, true><<<(NB + 63) / 64, 256>>>(nullptr, Wf);
    k_attn_final<<<(NB + 255) / 256, 256>>>(asf, adf);
    k_agg_final<<<AGG_GRID, 256>>>(bf, batch);

    // linear head
    k_final<<<1, 256>>>(Wl, bl, out);
}

// round 11
// speedup vs baseline: 1.0096x; 1.0096x over previous
#include <cuda_runtime.h>

#define NB 50000
#define EE 1600000
#define ET (EE + NB)
#define GG 128

// ---------------- device scratch (no allocations allowed) ----------------
__device__ __align__(16) int    g_csr[ET];          // src ids sorted by dst
__device__ __align__(16) int    g_deg[NB + 1];
__device__ __align__(16) int    g_off[NB + 1];
__device__ __align__(16) int    g_cur[NB];
__device__ __align__(16) float  g_h[NB * 64];       // W-transformed features (fp32)
__device__ __align__(16) float  g_act[NB * 64];     // activated layer output / next input
__device__ __align__(16) float4 g_asrc4[NB * 8];    // (asrc, exp(asrc), exp(0.2*asrc), -)
__device__ __align__(16) float  g_adst[NB * 8];
__device__ __align__(16) float  g_pool[GG * 32];
__device__ __align__(16) float  g_cnt[GG];

// ---------------- graph build ----------------
__global__ void k_zero() {
    int i = blockIdx.x * blockDim.x + threadIdx.x;
    if (i <= NB) g_deg[i] = 0;
    if (i < GG * 32) g_pool[i] = 0.f;
    if (i < GG) g_cnt[i] = 0.f;
}

__global__ void k_count(const int* __restrict__ ei) {
    int i = blockIdx.x * blockDim.x + threadIdx.x;
    if (i >= ET) return;
    int d = (i < EE) ? ei[EE + i] : (i - EE);
    atomicAdd(&g_deg[d], 1);
}

__global__ void k_scan() {   // 1 block, 1024 threads: exclusive scan of g_deg
    __shared__ int sm[1024];
    const int C = 49;                       // 49*1024 >= NB
    int t = threadIdx.x;
    int start = t * C;
    int end = min(start + C, NB);
    int sum = 0;
    for (int i = start; i < end; i++) sum += g_deg[i];
    sm[t] = sum;
    __syncthreads();
    for (int d = 1; d < 1024; d <<= 1) {
        int v = (t >= d) ? sm[t - d] : 0;
        __syncthreads();
        sm[t] += v;
        __syncthreads();
    }
    int run = (t == 0) ? 0 : sm[t - 1];
    for (int i = start; i < end; i++) {
        g_off[i] = run; g_cur[i] = run;
        run += g_deg[i];
    }
    if (t == 0) g_off[NB] = sm[1023];
}

__global__ void k_scatter(const int* __restrict__ ei) {
    int i = blockIdx.x * blockDim.x + threadIdx.x;
    if (i >= ET) return;
    int s, d;
    if (i < EE) { s = ei[i]; d = ei[EE + i]; }
    else        { s = i - EE; d = s; }
    int pos = atomicAdd(&g_cur[d], 1);
    g_csr[pos] = s;
}

// ---------------- dense: h = X @ W  (writes g_h) ----------------
template <int K, int J, int RB, bool USE_ACT>
__global__ void k_gemm(const float* __restrict__ Xparam, const float* __restrict__ W) {
    const float* __restrict__ X = USE_ACT ? (const float*)g_act : Xparam;
    constexpr int CG = J / 4;                 // column groups (4 cols each)
    constexpr int RPT = RB * CG / 256;        // rows per thread
    __shared__ float sW[K * J];
    __shared__ float sX[RB * K];
    int t = threadIdx.x;
    int row0 = blockIdx.x * RB;
    for (int i = t; i < K * J; i += 256) sW[i] = W[i];
    int nrows = min(RB, NB - row0);
    for (int i = t; i < nrows * K; i += 256) sX[i] = X[(size_t)row0 * K + i];
    __syncthreads();

    int rg = t / CG, cg = t % CG;
    float acc[RPT][4];
#pragma unroll
    for (int r = 0; r < RPT; r++)
#pragma unroll
        for (int q = 0; q < 4; q++) acc[r][q] = 0.f;

#pragma unroll 8
    for (int k = 0; k < K; k++) {
        float xs[RPT];
#pragma unroll
        for (int r = 0; r < RPT; r++) xs[r] = sX[(rg * RPT + r) * K + k];
#pragma unroll
        for (int q = 0; q < 4; q++) {
            float w = sW[k * J + cg + CG * q];
#pragma unroll
            for (int r = 0; r < RPT; r++) acc[r][q] = fmaf(xs[r], w, acc[r][q]);
        }
    }
#pragma unroll
    for (int r = 0; r < RPT; r++) {
        int row = row0 + rg * RPT + r;
        if (row < NB) {
#pragma unroll
            for (int q = 0; q < 4; q++) g_h[(size_t)row * J + cg + CG * q] = acc[r][q];
        }
    }
}

// ---------------- attention coefficients (8 heads x 8 ch) ----------------
// Writes (asrc, exp(asrc), exp(0.2*asrc)) so the edge loop needs no MUFU.
__global__ void k_attn(const float* __restrict__ As, const float* __restrict__ Ad) {
    int idx = blockIdx.x * blockDim.x + threadIdx.x;   // n*8 + head
    if (idx >= NB * 8) return;
    int h = idx & 7;
    const float4* hp = (const float4*)(g_h + (size_t)idx * 8);
    float4 v0 = hp[0], v1 = hp[1];
    const float4* ap = (const float4*)(As + h * 8);
    float4 a0 = __ldg(ap), a1 = __ldg(ap + 1);
    const float4* bp = (const float4*)(Ad + h * 8);
    float4 c0 = __ldg(bp), c1 = __ldg(bp + 1);
    float a = v0.x*a0.x + v0.y*a0.y + v0.z*a0.z + v0.w*a0.w
            + v1.x*a1.x + v1.y*a1.y + v1.z*a1.z + v1.w*a1.w;
    g_asrc4[idx] = make_float4(a, __expf(a), __expf(0.2f * a), 0.f);
    g_adst[idx] = v0.x*c0.x + v0.y*c0.y + v0.z*c0.z + v0.w*c0.w
                + v1.x*c1.x + v1.y*c1.y + v1.z*c1.z + v1.w*c1.w;
}

// ---------------- softmax-aggregate: warp per dst node, single pass, no MUFU ----------------
// p = exp(leaky(a+b)) = (a+b>=0) ? exp(a)exp(b) : exp(.2a)exp(.2b)
__global__ void k_agg(const float* __restrict__ B) {
    int gw = (blockIdx.x * blockDim.x + threadIdx.x) >> 5;
    if (gw >= NB) return;
    int lane = threadIdx.x & 31;
    int head = lane >> 2;
    int begin = g_off[gw], end = g_off[gw + 1];
    float ad = g_adst[gw * 8 + head];
    float B1 = __expf(ad);              // once per node
    float B2 = __expf(0.2f * ad);
    int j = lane * 2;                   // channel pair: head*8 + (lane%4)*2

    float s = 0.f, ax = 0.f, ay = 0.f;
    for (int i = begin; i < end; i++) {
        int src = __ldg(&g_csr[i]);
        float4 v = __ldg(&g_asrc4[src * 8 + head]);
        float p = (v.x + ad >= 0.f) ? v.y * B1 : v.z * B2;
        float2 hv = __ldg((const float2*)(g_h + (size_t)src * 64 + j));
        s += p;
        ax = fmaf(p, hv.x, ax);
        ay = fmaf(p, hv.y, ay);
    }
    float inv = 1.f / (s + 1e-16f);
    float ox = ax * inv + B[j];
    float oy = ay * inv + B[j + 1];
    ox = (ox > 0.f) ? ox : (__expf(ox) - 1.f);     // ELU
    oy = (oy > 0.f) ? oy : (__expf(oy) - 1.f);
    *(float2*)(g_act + (size_t)gw * 64 + j) = make_float2(ox, oy);
}

// ---------------- final layer: 1 head, 32 channels ----------------
__global__ void k_attn_final(const float* __restrict__ As, const float* __restrict__ Ad) {
    int n = blockIdx.x * blockDim.x + threadIdx.x;
    if (n >= NB) return;
    const float4* hp = (const float4*)(g_h + (size_t)n * 32);
    float s = 0.f, d = 0.f;
#pragma unroll
    for (int q = 0; q < 8; q++) {
        float4 hv = hp[q];
        float4 av = __ldg((const float4*)As + q);
        float4 dv = __ldg((const float4*)Ad + q);
        s += hv.x*av.x + hv.y*av.y + hv.z*av.z + hv.w*av.w;
        d += hv.x*dv.x + hv.y*dv.y + hv.z*dv.z + hv.w*dv.w;
    }
    g_asrc4[n] = make_float4(s, __expf(s), __expf(0.2f * s), 0.f);
    g_adst[n] = d;
}

// single pass + fused global mean-pool accumulation, no MUFU in loop
__global__ void k_agg_final(const float* __restrict__ Bf, const int* __restrict__ batch) {
    int gw = (blockIdx.x * blockDim.x + threadIdx.x) >> 5;
    if (gw >= NB) return;
    int lane = threadIdx.x & 31;
    int begin = g_off[gw], end = g_off[gw + 1];
    float ad = g_adst[gw];
    float B1 = __expf(ad);
    float B2 = __expf(0.2f * ad);

    float s = 0.f, acc = 0.f;
    for (int i = begin; i < end; i++) {
        int src = __ldg(&g_csr[i]);
        float4 v = __ldg(&g_asrc4[src]);
        float p = (v.x + ad >= 0.f) ? v.y * B1 : v.z * B2;
        s += p;
        acc = fmaf(p, __ldg(&g_h[(size_t)src * 32 + lane]), acc);
    }
    float o = acc / (s + 1e-16f) + Bf[lane];
    int g = batch[gw];
    atomicAdd(&g_pool[g * 32 + lane], o);
    if (lane == 0) atomicAdd(&g_cnt[g], 1.f);
}

// ---------------- head ----------------
__global__ void k_final(const float* __restrict__ Wl, const float* __restrict__ bl,
                        float* __restrict__ out) {
    int t = blockIdx.x * blockDim.x + threadIdx.x;
    if (t >= GG * 2) return;
    int g = t >> 1, o = t & 1;
    float cnt = fmaxf(g_cnt[g], 1.f);
    float acc = 0.f;
#pragma unroll
    for (int c = 0; c < 32; c++) acc += g_pool[g * 32 + c] * Wl[c * 2 + o];
    out[t] = acc / cnt + bl[o];
}

// ---------------- launcher ----------------
extern "C" void kernel_launch(void* const* d_in, const int* in_sizes, int n_in,
                              void* d_out, int out_size) {
    const float* x     = (const float*)d_in[0];
    const int*   ei    = (const int*)d_in[1];      // int32
    const int*   batch = (const int*)d_in[2];      // int32
    const float* W0 = (const float*)d_in[3];
    const float* as0 = (const float*)d_in[4];
    const float* ad0 = (const float*)d_in[5];
    const float* b0 = (const float*)d_in[6];
    const float* W1 = (const float*)d_in[7];
    const float* as1 = (const float*)d_in[8];
    const float* ad1 = (const float*)d_in[9];
    const float* b1 = (const float*)d_in[10];
    const float* W2 = (const float*)d_in[11];
    const float* as2 = (const float*)d_in[12];
    const float* ad2 = (const float*)d_in[13];
    const float* b2 = (const float*)d_in[14];
    const float* Wf = (const float*)d_in[15];
    const float* asf = (const float*)d_in[16];
    const float* adf = (const float*)d_in[17];
    const float* bf = (const float*)d_in[18];
    const float* Wl = (const float*)d_in[19];
    const float* bl = (const float*)d_in[20];
    float* out = (float*)d_out;

    // graph prep (dst is identical across layers -> one CSR build per launch)
    k_zero<<<(NB + 256) / 256, 256>>>();
    k_count<<<(ET + 255) / 256, 256>>>(ei);
    k_scan<<<1, 1024>>>();
    k_scatter<<<(ET + 255) / 256, 256>>>(ei);

    const int ATTN_GRID = (NB * 8 + 255) / 256;
    const int AGG_GRID  = (NB * 32 + 255) / 256;

    // layer 0: 128 -> 8x8   (RB=32: 48KB smem)
    k_gemm<128, 64, 32, false><<<(NB + 31) / 32, 256>>>(x, W0);
    k_attn<<<ATTN_GRID, 256>>>(as0, ad0);
    k_agg<<<AGG_GRID, 256>>>(b0);
    // layer 1  (RB=64: 32KB smem)
    k_gemm<64, 64, 64, true><<<(NB + 63) / 64, 256>>>(nullptr, W1);
    k_attn<<<ATTN_GRID, 256>>>(as1, ad1);
    k_agg<<<AGG_GRID, 256>>>(b1);
    // layer 2
    k_gemm<64, 64, 64, true><<<(NB + 63) / 64, 256>>>(nullptr, W2);
    k_attn<<<ATTN_GRID, 256>>>(as2, ad2);
    k_agg<<<AGG_GRID, 256>>>(b2);
    // final conv: 64 -> 32, 1 head
    k_gemm<64, 32, 64, true><<<(NB + 63) / 64, 256>>>(nullptr, Wf);
    k_attn_final<<<(NB + 255) / 256, 256>>>(asf, adf);
    k_agg_final<<<AGG_GRID, 256>>>(bf, batch);

    // linear head
    k_final<<<1, 256>>>(Wl, bl, out);
}

// round 12
// speedup vs baseline: 1.0727x; 1.0625x over previous
#include <cuda_runtime.h>

#define NB 50000
#define EE 1600000
#define ET (EE + NB)
#define GG 128

// ---------------- device scratch (no allocations allowed) ----------------
__device__ __align__(16) int    g_csr[ET];          // src ids sorted by dst
__device__ __align__(16) int    g_deg[NB + 1];
__device__ __align__(16) int    g_off[NB + 1];
__device__ __align__(16) int    g_cur[NB];
__device__ __align__(16) float  g_h[NB * 64];       // W-transformed features
__device__ __align__(16) float  g_act[NB * 64];     // activated layer output / next input
__device__ __align__(16) float  g_asrc[NB * 8];
__device__ __align__(16) float  g_adst[NB * 8];
__device__ __align__(16) float  g_pool[GG * 32];
__device__ __align__(16) float  g_cnt[GG];

// ---------------- graph build ----------------
__global__ void k_zero() {
    int i = blockIdx.x * blockDim.x + threadIdx.x;
    if (i <= NB) g_deg[i] = 0;
    if (i < GG * 32) g_pool[i] = 0.f;
    if (i < GG) g_cnt[i] = 0.f;
}

__global__ void k_count(const int* __restrict__ ei) {
    int i = blockIdx.x * blockDim.x + threadIdx.x;
    if (i >= ET) return;
    int d = (i < EE) ? ei[EE + i] : (i - EE);
    atomicAdd(&g_deg[d], 1);
}

__global__ void k_scan() {   // 1 block, 1024 threads: exclusive scan of g_deg
    __shared__ int sm[1024];
    const int C = 49;                       // 49*1024 >= NB
    int t = threadIdx.x;
    int start = t * C;
    int end = min(start + C, NB);
    int sum = 0;
    for (int i = start; i < end; i++) sum += g_deg[i];
    sm[t] = sum;
    __syncthreads();
    for (int d = 1; d < 1024; d <<= 1) {
        int v = (t >= d) ? sm[t - d] : 0;
        __syncthreads();
        sm[t] += v;
        __syncthreads();
    }
    int run = (t == 0) ? 0 : sm[t - 1];
    for (int i = start; i < end; i++) {
        g_off[i] = run; g_cur[i] = run;
        run += g_deg[i];
    }
    if (t == 0) g_off[NB] = sm[1023];
}

__global__ void k_scatter(const int* __restrict__ ei) {
    int i = blockIdx.x * blockDim.x + threadIdx.x;
    if (i >= ET) return;
    int s, d;
    if (i < EE) { s = ei[i]; d = ei[EE + i]; }
    else        { s = i - EE; d = s; }
    int pos = atomicAdd(&g_cur[d], 1);
    g_csr[pos] = s;
}

// ---------------- dense: h = X @ W  + fused attention-coefficient epilogue ------
// Each thread owns 4 CONTIGUOUS output columns (cg*4..cg*4+3): W loads are
// LDS.128, and each 8-wide head spans exactly 2 adjacent lanes, so asrc/adst
// reduce with one shfl_xor(1). J==32 path: 1 head over 8 lanes, 3 shfl rounds.
template <int K, int J, int RB, bool USE_ACT>
__global__ void k_gemm(const float* __restrict__ Xparam, const float* __restrict__ W,
                       const float* __restrict__ As, const float* __restrict__ Ad) {
    const float* __restrict__ X = USE_ACT ? (const float*)g_act : Xparam;
    constexpr int CG = J / 4;                 // column groups (4 contiguous cols)
    constexpr int RPT = RB * CG / 256;        // rows per thread
    __shared__ float sW[K * J];
    __shared__ float sX[RB * K];
    int t = threadIdx.x;
    int row0 = blockIdx.x * RB;
    for (int i = t; i < K * J; i += 256) sW[i] = W[i];
    int nrows = min(RB, NB - row0);
    for (int i = t; i < nrows * K; i += 256) sX[i] = X[(size_t)row0 * K + i];
    __syncthreads();

    int rg = t / CG, cg = t % CG;
    float acc[RPT][4];
#pragma unroll
    for (int r = 0; r < RPT; r++)
#pragma unroll
        for (int q = 0; q < 4; q++) acc[r][q] = 0.f;

#pragma unroll 8
    for (int k = 0; k < K; k++) {
        float4 w = *(const float4*)&sW[k * J + cg * 4];
#pragma unroll
        for (int r = 0; r < RPT; r++) {
            float xv = sX[(rg * RPT + r) * K + k];
            acc[r][0] = fmaf(xv, w.x, acc[r][0]);
            acc[r][1] = fmaf(xv, w.y, acc[r][1]);
            acc[r][2] = fmaf(xv, w.z, acc[r][2]);
            acc[r][3] = fmaf(xv, w.w, acc[r][3]);
        }
    }

    // attention-coefficient vectors for this thread's 4 columns
    float4 asv, adv;
    if (J == 64) {
        int h = cg >> 1;
        asv = __ldg((const float4*)(As + h * 8 + (cg & 1) * 4));
        adv = __ldg((const float4*)(Ad + h * 8 + (cg & 1) * 4));
    } else {
        asv = __ldg((const float4*)(As + cg * 4));
        adv = __ldg((const float4*)(Ad + cg * 4));
    }

#pragma unroll
    for (int r = 0; r < RPT; r++) {
        float pa = acc[r][0]*asv.x + acc[r][1]*asv.y + acc[r][2]*asv.z + acc[r][3]*asv.w;
        float pd = acc[r][0]*adv.x + acc[r][1]*adv.y + acc[r][2]*adv.z + acc[r][3]*adv.w;
        if (J == 64) {
            pa += __shfl_xor_sync(0xffffffffu, pa, 1);
            pd += __shfl_xor_sync(0xffffffffu, pd, 1);
        } else {
#pragma unroll
            for (int ofs = 1; ofs < 8; ofs <<= 1) {
                pa += __shfl_xor_sync(0xffffffffu, pa, ofs);
                pd += __shfl_xor_sync(0xffffffffu, pd, ofs);
            }
        }
        int row = row0 + rg * RPT + r;
        if (row < NB) {
            *(float4*)&g_h[(size_t)row * J + cg * 4] =
                make_float4(acc[r][0], acc[r][1], acc[r][2], acc[r][3]);
            if (J == 64) {
                if ((cg & 1) == 0) {
                    int h = cg >> 1;
                    g_asrc[row * 8 + h] = pa;
                    g_adst[row * 8 + h] = pd;
                }
            } else {
                if (cg == 0) { g_asrc[row] = pa; g_adst[row] = pd; }
            }
        }
    }
}

// ---------------- softmax-aggregate: warp per dst node, single pass (R8 form) ----
// exp(e)/sum == exp(e-max)/sum(exp(e-max)); |e| is O(10), clamp at 80 as guard.
__global__ void k_agg(const float* __restrict__ B) {
    int gw = (blockIdx.x * blockDim.x + threadIdx.x) >> 5;
    if (gw >= NB) return;
    int lane = threadIdx.x & 31;
    int head = lane >> 2;
    int begin = g_off[gw], end = g_off[gw + 1];
    float ad = g_adst[gw * 8 + head];
    int j = lane * 2;                              // channel pair: head*8 + (lane%4)*2

    float s = 0.f, ax = 0.f, ay = 0.f;
    for (int i = begin; i < end; i++) {
        int src = __ldg(&g_csr[i]);
        float e = __ldg(&g_asrc[src * 8 + head]) + ad;
        e = (e >= 0.f) ? e : 0.2f * e;
        float p = __expf(fminf(e, 80.f));
        float2 hv = __ldg((const float2*)(g_h + (size_t)src * 64 + j));
        s += p;
        ax = fmaf(p, hv.x, ax);
        ay = fmaf(p, hv.y, ay);
    }
    float inv = 1.f / (s + 1e-16f);
    float ox = ax * inv + B[j];
    float oy = ay * inv + B[j + 1];
    ox = (ox > 0.f) ? ox : (__expf(ox) - 1.f);     // ELU
    oy = (oy > 0.f) ? oy : (__expf(oy) - 1.f);
    *(float2*)(g_act + (size_t)gw * 64 + j) = make_float2(ox, oy);
}

// single pass + fused global mean-pool accumulation (R8 form)
__global__ void k_agg_final(const float* __restrict__ Bf, const int* __restrict__ batch) {
    int gw = (blockIdx.x * blockDim.x + threadIdx.x) >> 5;
    if (gw >= NB) return;
    int lane = threadIdx.x & 31;
    int begin = g_off[gw], end = g_off[gw + 1];
    float ad = g_adst[gw];

    float s = 0.f, acc = 0.f;
    for (int i = begin; i < end; i++) {
        int src = __ldg(&g_csr[i]);
        float e = __ldg(&g_asrc[src]) + ad;
        e = (e >= 0.f) ? e : 0.2f * e;
        float p = __expf(fminf(e, 80.f));
        s += p;
        acc = fmaf(p, __ldg(&g_h[(size_t)src * 32 + lane]), acc);
    }
    float o = acc / (s + 1e-16f) + Bf[lane];
    int g = batch[gw];
    atomicAdd(&g_pool[g * 32 + lane], o);
    if (lane == 0) atomicAdd(&g_cnt[g], 1.f);
}

// ---------------- head ----------------
__global__ void k_final(const float* __restrict__ Wl, const float* __restrict__ bl,
                        float* __restrict__ out) {
    int t = blockIdx.x * blockDim.x + threadIdx.x;
    if (t >= GG * 2) return;
    int g = t >> 1, o = t & 1;
    float cnt = fmaxf(g_cnt[g], 1.f);
    float acc = 0.f;
#pragma unroll
    for (int c = 0; c < 32; c++) acc += g_pool[g * 32 + c] * Wl[c * 2 + o];
    out[t] = acc / cnt + bl[o];
}

// ---------------- launcher ----------------
extern "C" void kernel_launch(void* const* d_in, const int* in_sizes, int n_in,
                              void* d_out, int out_size) {
    const float* x     = (const float*)d_in[0];
    const int*   ei    = (const int*)d_in[1];      // int32
    const int*   batch = (const int*)d_in[2];      // int32
    const float* W0 = (const float*)d_in[3];
    const float* as0 = (const float*)d_in[4];
    const float* ad0 = (const float*)d_in[5];
    const float* b0 = (const float*)d_in[6];
    const float* W1 = (const float*)d_in[7];
    const float* as1 = (const float*)d_in[8];
    const float* ad1 = (const float*)d_in[9];
    const float* b1 = (const float*)d_in[10];
    const float* W2 = (const float*)d_in[11];
    const float* as2 = (const float*)d_in[12];
    const float* ad2 = (const float*)d_in[13];
    const float* b2 = (const float*)d_in[14];
    const float* Wf = (const float*)d_in[15];
    const float* asf = (const float*)d_in[16];
    const float* adf = (const float*)d_in[17];
    const float* bf = (const float*)d_in[18];
    const float* Wl = (const float*)d_in[19];
    const float* bl = (const float*)d_in[20];
    float* out = (float*)d_out;

    // graph prep (dst is identical across layers -> one CSR build per launch)
    k_zero<<<(NB + 256) / 256, 256>>>();
    k_count<<<(ET + 255) / 256, 256>>>(ei);
    k_scan<<<1, 1024>>>();
    k_scatter<<<(ET + 255) / 256, 256>>>(ei);

    const int AGG_GRID = (NB * 32 + 255) / 256;

    // layer 0: 128 -> 8x8   (RB=32: 48KB smem)
    k_gemm<128, 64, 32, false><<<(NB + 31) / 32, 256>>>(x, W0, as0, ad0);
    k_agg<<<AGG_GRID, 256>>>(b0);
    // layer 1  (RB=64: 32KB smem)
    k_gemm<64, 64, 64, true><<<(NB + 63) / 64, 256>>>(nullptr, W1, as1, ad1);
    k_agg<<<AGG_GRID, 256>>>(b1);
    // layer 2
    k_gemm<64, 64, 64, true><<<(NB + 63) / 64, 256>>>(nullptr, W2, as2, ad2);
    k_agg<<<AGG_GRID, 256>>>(b2);
    // final conv: 64 -> 32, 1 head
    k_gemm<64, 32, 64, true><<<(NB + 63) / 64, 256>>>(nullptr, Wf, asf, adf);
    k_agg_final<<<AGG_GRID, 256>>>(bf, batch);

    // linear head
    k_final<<<1, 256>>>(Wl, bl, out);
}